// round 3
// baseline (speedup 1.0000x reference)
#include <cuda_runtime.h>

// CRF token-classifier NLL, single fused kernel. B=64,S=512,H=768,L=3 -> scalar.
// Per (batch, 64-step chunk) block: emissions (hidden@W+b), log-semiring 3x3
// matrix tree reduction, gold-score partial, local last-mask index.
// The LAST finishing block (atomic counter) runs the cross-chunk epilogue.

#define Bn 64
#define Sn 512
#define Hn 768
#define CHUNK 64
#define NCH (Sn / CHUNK) // 8
#define T1 256

// scratch (no allocations allowed)
__device__ float g_M[Bn][NCH][9];
__device__ float g_gold[Bn][NCH];
__device__ float g_alpha0[Bn][3];
__device__ int   g_last[Bn][NCH];
__device__ unsigned int g_ctr = 0;

__device__ __forceinline__ float lse3(float a, float b, float c) {
    float m = fmaxf(a, fmaxf(b, c));
    return m + __logf(__expf(a - m) + __expf(b - m) + __expf(c - m));
}

// log-semiring 3x3 product: R = A (*) B,  R[i][k] = lse_j(A[i][j]+B[j][k])
__device__ __forceinline__ void semiprod(const float* A, const float* B, float* R) {
    #pragma unroll
    for (int i = 0; i < 3; i++)
        #pragma unroll
        for (int k = 0; k < 3; k++)
            R[i * 3 + k] = lse3(A[i * 3 + 0] + B[0 + k],
                                A[i * 3 + 1] + B[3 + k],
                                A[i * 3 + 2] + B[6 + k]);
}

__global__ __launch_bounds__(T1) void crf_fused(
    const float* __restrict__ hidden, const float* __restrict__ W,
    const float* __restrict__ bias, const float* __restrict__ start,
    const float* __restrict__ endt, const float* __restrict__ trans,
    const int* __restrict__ mask, const int* __restrict__ labels,
    float* __restrict__ out)
{
    const int chunk = blockIdx.x;
    const int batch = blockIdx.y;
    const int tid = threadIdx.x, lane = tid & 31, wid = tid >> 5;

    __shared__ float w0[Hn], w1[Hn], w2[Hn];   // W transposed (conflict-free)
    __shared__ float em[CHUNK][4];             // emissions for this chunk
    __shared__ float mats[CHUNK][9];           // log-semiring matrices
    __shared__ float tmp[CHUNK / 2][9];
    __shared__ float sgold[2];
    __shared__ int   slast[2];
    __shared__ float str[9];
    __shared__ int   s_is_last;
    __shared__ float sred[2];

    // stage W (transposed) and transitions
    for (int i = tid; i < Hn; i += T1) {
        w0[i] = W[i * 3 + 0];
        w1[i] = W[i * 3 + 1];
        w2[i] = W[i * 3 + 2];
    }
    if (tid < 9) str[tid] = trans[tid];
    __syncthreads();

    const float* hb = hidden + ((size_t)batch * Sn + (size_t)chunk * CHUNK) * Hn;
    float bb[3] = {bias[0], bias[1], bias[2]};

    // ---- emissions: warp handles groups of 4 timesteps; lane covers
    //      h = 4*lane + 128*k. float4 GMEM loads; W LDS amortized x4.
    for (int g = wid; g < CHUNK / 4; g += 8) {
        const int s0 = g * 4;
        float acc[4][3];
        #pragma unroll
        for (int t = 0; t < 4; t++)
            #pragma unroll
            for (int j = 0; j < 3; j++) acc[t][j] = 0.0f;

        #pragma unroll
        for (int k = 0; k < 6; k++) {
            const int h = 4 * lane + 128 * k;
            float4 v0 = *(const float4*)(w0 + h);
            float4 v1 = *(const float4*)(w1 + h);
            float4 v2 = *(const float4*)(w2 + h);
            #pragma unroll
            for (int t = 0; t < 4; t++) {
                float4 x = *(const float4*)(hb + (size_t)(s0 + t) * Hn + h);
                acc[t][0] += x.x * v0.x + x.y * v0.y + x.z * v0.z + x.w * v0.w;
                acc[t][1] += x.x * v1.x + x.y * v1.y + x.z * v1.z + x.w * v1.w;
                acc[t][2] += x.x * v2.x + x.y * v2.y + x.z * v2.z + x.w * v2.w;
            }
        }
        #pragma unroll
        for (int off = 16; off; off >>= 1)
            #pragma unroll
            for (int t = 0; t < 4; t++)
                #pragma unroll
                for (int j = 0; j < 3; j++)
                    acc[t][j] += __shfl_xor_sync(0xffffffffu, acc[t][j], off);
        if (lane == 0) {
            #pragma unroll
            for (int t = 0; t < 4; t++)
                #pragma unroll
                for (int j = 0; j < 3; j++)
                    em[s0 + t][j] = acc[t][j] + bb[j];
        }
    }
    __syncthreads();

    // ---- per-step matrices + gold partials + local last-mask index
    float gp = 0.0f;
    int   lc = -1;
    if (tid < CHUNK) {
        const int s = chunk * CHUNK + tid;
        const int mval = mask[batch * Sn + s];
        lc = (mval > 0) ? s : -1;
        const bool act = (s >= 1) && (mval > 0);
        float row[9];
        if (act) {
            #pragma unroll
            for (int i = 0; i < 3; i++)
                #pragma unroll
                for (int j = 0; j < 3; j++)
                    row[i * 3 + j] = str[i * 3 + j] + em[tid][j];
        } else {
            #pragma unroll
            for (int e = 0; e < 9; e++)
                row[e] = (e == 0 || e == 4 || e == 8) ? 0.0f : -1e30f;
        }
        #pragma unroll
        for (int e = 0; e < 9; e++) mats[tid][e] = row[e];

        if (s >= 1) {
            int lg = labels[batch * Sn + s];     int tg = lg < 0 ? 0 : lg;
            int lp = labels[batch * Sn + s - 1]; int tp = lp < 0 ? 0 : lp;
            float m = (mval > 0) ? 1.0f : 0.0f;
            gp = (em[tid][tg] + str[tp * 3 + tg]) * m;
        }
    }
    if (chunk == 0 && tid < 3)
        g_alpha0[batch][tid] = start[tid] + em[0][tid];

    if (wid < 2) {
        #pragma unroll
        for (int off = 16; off; off >>= 1) {
            gp += __shfl_xor_sync(0xffffffffu, gp, off);
            lc  = max(lc, __shfl_xor_sync(0xffffffffu, lc, off));
        }
        if (lane == 0) { sgold[wid] = gp; slast[wid] = lc; }
    }

    // ---- ordered tree reduction of the 64 log-semiring matrices
    for (int n = CHUNK; n > 1; n >>= 1) {
        __syncthreads();
        const int half = n >> 1;
        for (int idx = tid; idx < half * 9; idx += T1) {
            const int p = idx / 9, e = idx - p * 9;
            const int i = e / 3, kk = e - i * 3;
            float x0 = mats[2 * p][i * 3 + 0] + mats[2 * p + 1][0 + kk];
            float x1 = mats[2 * p][i * 3 + 1] + mats[2 * p + 1][3 + kk];
            float x2 = mats[2 * p][i * 3 + 2] + mats[2 * p + 1][6 + kk];
            tmp[p][e] = lse3(x0, x1, x2);
        }
        __syncthreads();
        for (int idx = tid; idx < half * 9; idx += T1) {
            const int p = idx / 9, e = idx - p * 9;
            mats[p][e] = tmp[p][e];
        }
    }
    __syncthreads();
    if (tid < 9) g_M[batch][chunk][tid] = mats[0][tid];
    if (tid == 0) {
        g_gold[batch][chunk] = sgold[0] + sgold[1];
        g_last[batch][chunk] = max(slast[0], slast[1]);
    }

    // ==== last-block-done epilogue ====
    __threadfence();
    if (tid == 0) {
        unsigned int n = atomicAdd(&g_ctr, 1u);
        s_is_last = (n == (unsigned)(NCH * Bn - 1)) ? 1 : 0;
    }
    __syncthreads();
    if (!s_is_last) return;
    if (tid == 0) g_ctr = 0;   // reset for next graph replay

    float val = 0.0f;
    if (tid < Bn) {
        const int b = tid;

        // load all 8 chunk matrices (L2-hot) with good MLP
        float m[NCH][9];
        #pragma unroll
        for (int c = 0; c < NCH; c++)
            #pragma unroll
            for (int e = 0; e < 9; e++)
                m[c][e] = __ldcg(&g_M[b][c][e]);

        // 3-level tree combine (order-preserving)
        float c01[9], c23[9], c45[9], c67[9], a[9], d[9], M[9];
        semiprod(m[0], m[1], c01); semiprod(m[2], m[3], c23);
        semiprod(m[4], m[5], c45); semiprod(m[6], m[7], c67);
        semiprod(c01, c23, a);     semiprod(c45, c67, d);
        semiprod(a, d, M);

        int last = 0;
        #pragma unroll
        for (int c = 0; c < NCH; c++) last = max(last, __ldcg(&g_last[b][c]));

        float al0 = __ldcg(&g_alpha0[b][0]);
        float al1 = __ldcg(&g_alpha0[b][1]);
        float al2 = __ldcg(&g_alpha0[b][2]);
        float af0 = lse3(al0 + M[0], al1 + M[3], al2 + M[6]);
        float af1 = lse3(al0 + M[1], al1 + M[4], al2 + M[7]);
        float af2 = lse3(al0 + M[2], al1 + M[5], al2 + M[8]);
        float e0 = endt[0], e1 = endt[1], e2 = endt[2];
        float logz = lse3(af0 + e0, af1 + e1, af2 + e2);

        int l0 = labels[(size_t)b * Sn];        int t0 = l0 < 0 ? 0 : l0;
        int ll = labels[(size_t)b * Sn + last]; int lt = ll < 0 ? 0 : ll;
        float et = (lt == 0) ? e0 : ((lt == 1) ? e1 : e2);
        float a0 = (t0 == 0) ? al0 : ((t0 == 1) ? al1 : al2);
        float score = a0 + et;
        #pragma unroll
        for (int c = 0; c < NCH; c++) score += __ldcg(&g_gold[b][c]);
        val = score - logz;
    }

    // mean over the 64 batch values (threads 0..63), negate
    if (wid < 2) {
        #pragma unroll
        for (int off = 16; off; off >>= 1)
            val += __shfl_xor_sync(0xffffffffu, val, off);
        if (lane == 0) sred[wid] = val;
    }
    __syncthreads();
    if (tid == 0) out[0] = -(sred[0] + sred[1]) * (1.0f / 64.0f);
}

extern "C" void kernel_launch(void* const* d_in, const int* in_sizes, int n_in,
                              void* d_out, int out_size) {
    const float* hidden = (const float*)d_in[0];
    const float* W      = (const float*)d_in[1];
    const float* bias   = (const float*)d_in[2];
    const float* start  = (const float*)d_in[3];
    const float* endt   = (const float*)d_in[4];
    const float* trans  = (const float*)d_in[5];
    const int*   mask   = (const int*)d_in[6];
    const int*   labels = (const int*)d_in[7];

    crf_fused<<<dim3(NCH, Bn), T1>>>(hidden, W, bias, start, endt, trans,
                                     mask, labels, (float*)d_out);
}

// round 4
// speedup vs baseline: 1.4070x; 1.4070x over previous
#include <cuda_runtime.h>

// CRF token-classifier NLL, single fused kernel. B=64,S=512,H=768,L=3 -> scalar.
// Per (batch, 64-step chunk) block: emissions (hidden@W+b), register-resident
// shfl-based log-semiring 3x3 reduce, gold partial, last-mask index.
// Last finishing block (atomic counter) runs the cross-chunk epilogue.

#define Bn 64
#define Sn 512
#define Hn 768
#define CHUNK 64
#define NCH (Sn / CHUNK) // 8
#define T1 256

// scratch (no allocations allowed)
__device__ float g_M[Bn][NCH][9];
__device__ float g_gold[Bn][NCH];
__device__ float g_alpha0[Bn][3];
__device__ int   g_last[Bn][NCH];
__device__ unsigned int g_ctr = 0;

__device__ __forceinline__ float lse3(float a, float b, float c) {
    float m = fmaxf(a, fmaxf(b, c));
    return m + __logf(__expf(a - m) + __expf(b - m) + __expf(c - m));
}

__global__ __launch_bounds__(T1, 4) void crf_fused(
    const float* __restrict__ hidden, const float* __restrict__ W,
    const float* __restrict__ bias, const float* __restrict__ start,
    const float* __restrict__ endt, const float* __restrict__ trans,
    const int* __restrict__ mask, const int* __restrict__ labels,
    float* __restrict__ out)
{
    const int chunk = blockIdx.x;
    const int batch = blockIdx.y;
    const int tid = threadIdx.x, lane = tid & 31, wid = tid >> 5;

    __shared__ float w0[Hn], w1[Hn], w2[Hn];   // W transposed (conflict-free)
    __shared__ float em[CHUNK][4];             // emissions for this chunk
    __shared__ float wprod[2][9];              // per-warp chunk products
    __shared__ float sgold[2];
    __shared__ int   slast[2];
    __shared__ float str[9];
    __shared__ int   s_is_last;
    __shared__ float sred[2];

    // stage W (transposed) and transitions
    for (int i = tid; i < Hn; i += T1) {
        w0[i] = W[i * 3 + 0];
        w1[i] = W[i * 3 + 1];
        w2[i] = W[i * 3 + 2];
    }
    if (tid < 9) str[tid] = trans[tid];
    __syncthreads();

    const float* hb = hidden + ((size_t)batch * Sn + (size_t)chunk * CHUNK) * Hn;
    float bb[3] = {bias[0], bias[1], bias[2]};

    // ---- emissions: warp handles groups of 4 timesteps; lane covers
    //      h = 4*lane + 128*k. Streaming float4 loads; W LDS amortized x4.
    for (int g = wid; g < CHUNK / 4; g += 8) {
        const int s0 = g * 4;
        float acc[4][3];
        #pragma unroll
        for (int t = 0; t < 4; t++)
            #pragma unroll
            for (int j = 0; j < 3; j++) acc[t][j] = 0.0f;

        #pragma unroll
        for (int k = 0; k < 6; k++) {
            const int h = 4 * lane + 128 * k;
            float4 v0 = *(const float4*)(w0 + h);
            float4 v1 = *(const float4*)(w1 + h);
            float4 v2 = *(const float4*)(w2 + h);
            #pragma unroll
            for (int t = 0; t < 4; t++) {
                float4 x = __ldcs((const float4*)(hb + (size_t)(s0 + t) * Hn + h));
                acc[t][0] += x.x * v0.x + x.y * v0.y + x.z * v0.z + x.w * v0.w;
                acc[t][1] += x.x * v1.x + x.y * v1.y + x.z * v1.z + x.w * v1.w;
                acc[t][2] += x.x * v2.x + x.y * v2.y + x.z * v2.z + x.w * v2.w;
            }
        }
        #pragma unroll
        for (int off = 16; off; off >>= 1)
            #pragma unroll
            for (int t = 0; t < 4; t++)
                #pragma unroll
                for (int j = 0; j < 3; j++)
                    acc[t][j] += __shfl_xor_sync(0xffffffffu, acc[t][j], off);
        if (lane == 0) {
            #pragma unroll
            for (int t = 0; t < 4; t++)
                #pragma unroll
                for (int j = 0; j < 3; j++)
                    em[s0 + t][j] = acc[t][j] + bb[j];
        }
    }
    __syncthreads();

    // ---- per-step matrices (registers) + gold partial + last-mask index
    float gp = 0.0f;
    int   lc = -1;
    float row[9];
    if (tid < CHUNK) {
        const int s = chunk * CHUNK + tid;
        const int mval = mask[batch * Sn + s];
        lc = (mval > 0) ? s : -1;
        const bool act = (s >= 1) && (mval > 0);
        if (act) {
            #pragma unroll
            for (int i = 0; i < 3; i++)
                #pragma unroll
                for (int j = 0; j < 3; j++)
                    row[i * 3 + j] = str[i * 3 + j] + em[tid][j];
        } else {
            #pragma unroll
            for (int e = 0; e < 9; e++)
                row[e] = (e == 0 || e == 4 || e == 8) ? 0.0f : -1e30f;
        }
        if (s >= 1) {
            int lg = labels[batch * Sn + s];     int tg = lg < 0 ? 0 : lg;
            int lp = labels[batch * Sn + s - 1]; int tp = lp < 0 ? 0 : lp;
            float m = (mval > 0) ? 1.0f : 0.0f;
            gp = (em[tid][tg] + str[tp * 3 + tg]) * m;
        }
    }
    if (chunk == 0 && tid < 3)
        g_alpha0[batch][tid] = start[tid] + em[0][tid];

    // ---- in-warp ordered log-semiring allgather-reduce (warps 0,1 = 64 steps)
    if (wid < 2) {
        #pragma unroll
        for (int l = 0; l < 5; l++) {
            float oth[9];
            #pragma unroll
            for (int e = 0; e < 9; e++)
                oth[e] = __shfl_xor_sync(0xffffffffu, row[e], 1 << l);
            const bool left = ((lane >> l) & 1) == 0;
            float A[9], Bm[9];
            #pragma unroll
            for (int e = 0; e < 9; e++) {
                A[e]  = left ? row[e] : oth[e];
                Bm[e] = left ? oth[e] : row[e];
            }
            #pragma unroll
            for (int i = 0; i < 3; i++)
                #pragma unroll
                for (int k = 0; k < 3; k++)
                    row[i * 3 + k] = lse3(A[i * 3 + 0] + Bm[0 + k],
                                          A[i * 3 + 1] + Bm[3 + k],
                                          A[i * 3 + 2] + Bm[6 + k]);
        }
        // gold + last reductions
        #pragma unroll
        for (int off = 16; off; off >>= 1) {
            gp += __shfl_xor_sync(0xffffffffu, gp, off);
            lc  = max(lc, __shfl_xor_sync(0xffffffffu, lc, off));
        }
        if (lane < 9) wprod[wid][lane] = row[lane];
        if (lane == 0) { sgold[wid] = gp; slast[wid] = lc; }
    }
    __syncthreads();

    // combine warp0 (left) with warp1 (right): one element per thread
    if (tid < 9) {
        const int i = tid / 3, k = tid - i * 3;
        g_M[batch][chunk][tid] = lse3(wprod[0][i * 3 + 0] + wprod[1][0 + k],
                                      wprod[0][i * 3 + 1] + wprod[1][3 + k],
                                      wprod[0][i * 3 + 2] + wprod[1][6 + k]);
    }
    if (tid == 0) {
        g_gold[batch][chunk] = sgold[0] + sgold[1];
        g_last[batch][chunk] = max(slast[0], slast[1]);
    }

    // ==== last-block-done epilogue ====
    __threadfence();
    if (tid == 0) {
        unsigned int n = atomicAdd(&g_ctr, 1u);
        s_is_last = (n == (unsigned)(NCH * Bn - 1)) ? 1 : 0;
    }
    __syncthreads();
    if (!s_is_last) return;
    if (tid == 0) g_ctr = 0;   // reset for next graph replay

    float val = 0.0f;
    if (tid < Bn) {
        const int b = tid;

        // streaming left-to-right combine (register-frugal)
        float M[9];
        #pragma unroll
        for (int e = 0; e < 9; e++) M[e] = __ldcg(&g_M[b][0][e]);
        #pragma unroll
        for (int c = 1; c < NCH; c++) {
            float Nm[9], R[9];
            #pragma unroll
            for (int e = 0; e < 9; e++) Nm[e] = __ldcg(&g_M[b][c][e]);
            #pragma unroll
            for (int i = 0; i < 3; i++)
                #pragma unroll
                for (int k = 0; k < 3; k++)
                    R[i * 3 + k] = lse3(M[i * 3 + 0] + Nm[0 + k],
                                        M[i * 3 + 1] + Nm[3 + k],
                                        M[i * 3 + 2] + Nm[6 + k]);
            #pragma unroll
            for (int e = 0; e < 9; e++) M[e] = R[e];
        }

        int last = 0;
        #pragma unroll
        for (int c = 0; c < NCH; c++) last = max(last, __ldcg(&g_last[b][c]));

        float al0 = __ldcg(&g_alpha0[b][0]);
        float al1 = __ldcg(&g_alpha0[b][1]);
        float al2 = __ldcg(&g_alpha0[b][2]);
        float af0 = lse3(al0 + M[0], al1 + M[3], al2 + M[6]);
        float af1 = lse3(al0 + M[1], al1 + M[4], al2 + M[7]);
        float af2 = lse3(al0 + M[2], al1 + M[5], al2 + M[8]);
        float e0 = endt[0], e1 = endt[1], e2 = endt[2];
        float logz = lse3(af0 + e0, af1 + e1, af2 + e2);

        int l0 = labels[(size_t)b * Sn];        int t0 = l0 < 0 ? 0 : l0;
        int ll = labels[(size_t)b * Sn + last]; int lt = ll < 0 ? 0 : ll;
        float et = (lt == 0) ? e0 : ((lt == 1) ? e1 : e2);
        float a0 = (t0 == 0) ? al0 : ((t0 == 1) ? al1 : al2);
        float score = a0 + et;
        #pragma unroll
        for (int c = 0; c < NCH; c++) score += __ldcg(&g_gold[b][c]);
        val = score - logz;
    }

    if (wid < 2) {
        #pragma unroll
        for (int off = 16; off; off >>= 1)
            val += __shfl_xor_sync(0xffffffffu, val, off);
        if (lane == 0) sred[wid] = val;
    }
    __syncthreads();
    if (tid == 0) out[0] = -(sred[0] + sred[1]) * (1.0f / 64.0f);
}

extern "C" void kernel_launch(void* const* d_in, const int* in_sizes, int n_in,
                              void* d_out, int out_size) {
    const float* hidden = (const float*)d_in[0];
    const float* W      = (const float*)d_in[1];
    const float* bias   = (const float*)d_in[2];
    const float* start  = (const float*)d_in[3];
    const float* endt   = (const float*)d_in[4];
    const float* trans  = (const float*)d_in[5];
    const int*   mask   = (const int*)d_in[6];
    const int*   labels = (const int*)d_in[7];

    crf_fused<<<dim3(NCH, Bn), T1>>>(hidden, W, bias, start, endt, trans,
                                     mask, labels, (float*)d_out);
}